// round 6
// baseline (speedup 1.0000x reference)
#include <cuda_runtime.h>

// ---------------------------------------------------------------------------
// Att_mask: per batch item b (65536 of them):
//   Q = tanh(Aq @ x_b), K = tanh(Ak @ x_b), V = tanh(Av @ x_b)   ([32,16] each)
//   scores = Q K^T / sqrt(nn_b); attn = softmax(scores, axis=s)
//   o = attn @ V ; R = tanh(Ao @ o)  ([16])
//   out row (b = s*16+i): out[b,j] = (j==i) ? sum_j R2[j] : -R2[j],  R2 = R^2
//
// Strategy: one warp per batch item (lane = rank r), packed f32x2 FFMA
// (fma.rn.f32x2 -> FFMA2, 2x fp32 throughput), A matrices transposed in
// shared (conflict-free lane reads), x/K/V staged in per-warp shared.
// Online softmax (|score| <= 16 so exp never overflows; no max pass, no
// 32-register score array).
// ---------------------------------------------------------------------------

typedef unsigned long long u64;

__device__ __forceinline__ u64 ff2(u64 a, u64 b, u64 c) {
    u64 d; asm("fma.rn.f32x2 %0, %1, %2, %3;" : "=l"(d) : "l"(a), "l"(b), "l"(c)); return d;
}
__device__ __forceinline__ u64 mul2(u64 a, u64 b) {
    u64 d; asm("mul.rn.f32x2 %0, %1, %2;" : "=l"(d) : "l"(a), "l"(b)); return d;
}
__device__ __forceinline__ u64 dup2(float a) {
    u64 d; asm("mov.b64 %0, {%1, %1};" : "=l"(d) : "f"(a)); return d;
}
__device__ __forceinline__ float2 un2(u64 a) {
    float2 f; asm("mov.b64 {%0, %1}, %2;" : "=f"(f.x), "=f"(f.y) : "l"(a)); return f;
}
__device__ __forceinline__ u64 pk2(float x, float y) {
    u64 d; asm("mov.b64 %0, {%1, %2};" : "=l"(d) : "f"(x), "f"(y)); return d;
}
__device__ __forceinline__ float tanh_approx(float x) {
    float y; asm("tanh.approx.f32 %0, %1;" : "=f"(y) : "f"(x)); return y;
}

static constexpr int WARPS = 8;     // warps per block
static constexpr int NB    = 4;     // batch items per warp
// shared layout (floats):
//   sAq[64*32] sAk[64*32] sAv[64*32] sAo[32]   = 6176
//   per warp: x[64*16]=1024, K[32*18]=576, V[32*18]=576  -> 2176
static constexpr int A_FLOATS  = 3 * 2048 + 32;       // 6176
static constexpr int PW_FLOATS = 1024 + 576 + 576;    // 2176
static constexpr int SMEM_BYTES = (A_FLOATS + WARPS * PW_FLOATS) * 4;  // 94336

__global__ void __launch_bounds__(WARPS * 32, 2)
att_mask_kernel(const float* __restrict__ x, const float* __restrict__ L,
                const float* __restrict__ Aq, const float* __restrict__ Ak,
                const float* __restrict__ Av, const float* __restrict__ Ao,
                float* __restrict__ out)
{
    extern __shared__ float smem[];
    float* sAq = smem;            // [64][32], sAq[d*32+r] = Aq[r*64+d]
    float* sAk = smem + 2048;
    float* sAv = smem + 4096;
    float* sAo = smem + 6144;     // [32]

    const int tid = threadIdx.x;

    // Load A transposed: conflict-free broadcast-free lane-indexed reads later.
    for (int i = tid; i < 2048; i += WARPS * 32) {
        int d = i >> 5, r = i & 31;
        sAq[i] = Aq[r * 64 + d];
        sAk[i] = Ak[r * 64 + d];
        sAv[i] = Av[r * 64 + d];
    }
    if (tid < 32) sAo[tid] = Ao[tid];
    __syncthreads();

    const int w    = tid >> 5;
    const int lane = tid & 31;

    float* sx = smem + A_FLOATS + w * PW_FLOATS;   // [64][16]
    float* sK = sx + 1024;                         // [32] rows, stride 18
    float* sV = sK + 576;                          // [32] rows, stride 18

    const float aor = sAo[lane];

    for (int jj = 0; jj < NB; jj++) {
        const int b = (blockIdx.x * WARPS + w) * NB + jj;

        // --- stage x_b (64x16 fp32 = 4KB, contiguous) into shared ---
        {
            const float4* xg = (const float4*)(x + (size_t)b * 1024);
            float4* xs = (float4*)sx;
            #pragma unroll
            for (int i = 0; i < 8; i++)
                xs[i * 32 + lane] = xg[i * 32 + lane];
        }

        // --- num_neighbors from L[b,0,:] (values are exactly 0.0/1.0) ---
        float Lv = 0.0f;
        if (lane < 16) Lv = L[(size_t)b * 256 + lane];
        unsigned msk = __ballot_sync(0xffffffffu, Lv >= 1.0f);
        float nn = (float)(__popc(msk) + 1);
        float rs = rsqrtf(nn);
        __syncwarp();

        // --- projections: lane r accumulates Q/K/V row r over d, packed x2 ---
        u64 q[8], k[8], v[8];
        #pragma unroll
        for (int p = 0; p < 8; p++) { q[p] = 0ull; k[p] = 0ull; v[p] = 0ull; }

        #pragma unroll 4
        for (int d = 0; d < 64; d++) {
            const ulonglong2* xr = (const ulonglong2*)(sx + d * 16);
            ulonglong2 xa = xr[0], xb = xr[1], xc = xr[2], xd = xr[3];
            u64 aq = dup2(sAq[d * 32 + lane]);
            u64 ak = dup2(sAk[d * 32 + lane]);
            u64 av = dup2(sAv[d * 32 + lane]);
            q[0] = ff2(aq, xa.x, q[0]); q[1] = ff2(aq, xa.y, q[1]);
            q[2] = ff2(aq, xb.x, q[2]); q[3] = ff2(aq, xb.y, q[3]);
            q[4] = ff2(aq, xc.x, q[4]); q[5] = ff2(aq, xc.y, q[5]);
            q[6] = ff2(aq, xd.x, q[6]); q[7] = ff2(aq, xd.y, q[7]);
            k[0] = ff2(ak, xa.x, k[0]); k[1] = ff2(ak, xa.y, k[1]);
            k[2] = ff2(ak, xb.x, k[2]); k[3] = ff2(ak, xb.y, k[3]);
            k[4] = ff2(ak, xc.x, k[4]); k[5] = ff2(ak, xc.y, k[5]);
            k[6] = ff2(ak, xd.x, k[6]); k[7] = ff2(ak, xd.y, k[7]);
            v[0] = ff2(av, xa.x, v[0]); v[1] = ff2(av, xa.y, v[1]);
            v[2] = ff2(av, xb.x, v[2]); v[3] = ff2(av, xb.y, v[3]);
            v[4] = ff2(av, xc.x, v[4]); v[5] = ff2(av, xc.y, v[5]);
            v[6] = ff2(av, xd.x, v[6]); v[7] = ff2(av, xd.y, v[7]);
        }

        // --- tanh; fold 1/sqrt(nn) into Q; publish K,V rows to shared ---
        {
            u64 rs2 = dup2(rs);
            #pragma unroll
            for (int p = 0; p < 8; p++) {
                float2 fq = un2(q[p]);
                q[p] = mul2(pk2(tanh_approx(fq.x), tanh_approx(fq.y)), rs2);
                float2 fk = un2(k[p]);
                *(u64*)(sK + lane * 18 + 2 * p) = pk2(tanh_approx(fk.x), tanh_approx(fk.y));
                float2 fv = un2(v[p]);
                *(u64*)(sV + lane * 18 + 2 * p) = pk2(tanh_approx(fv.x), tanh_approx(fv.y));
            }
        }
        __syncwarp();

        // --- fused scores + softmax-numerator + o accumulation ---
        // |score| <= n / sqrt(nn) <= 16 -> exp() safe without max subtraction.
        u64 o[8];
        #pragma unroll
        for (int p = 0; p < 8; p++) o[p] = 0ull;
        float esum = 0.0f;

        #pragma unroll 4
        for (int s = 0; s < 32; s++) {
            const u64* kr = (const u64*)(sK + s * 18);
            u64 acc = mul2(q[0], kr[0]);
            #pragma unroll
            for (int p = 1; p < 8; p++) acc = ff2(q[p], kr[p], acc);
            float2 a2 = un2(acc);
            float e = __expf(a2.x + a2.y);
            esum += e;
            u64 e2 = dup2(e);
            const u64* vr = (const u64*)(sV + s * 18);
            #pragma unroll
            for (int p = 0; p < 8; p++) o[p] = ff2(e2, vr[p], o[p]);
        }

        // --- contribution c[r][n] = (Ao[r]/esum) * o[r][n], reduce over r ---
        float coef = aor / esum;
        u64 c2 = dup2(coef);
        __syncwarp();                       // done reading sK rows
        #pragma unroll
        for (int p = 0; p < 8; p++)
            *(u64*)(sK + lane * 18 + 2 * p) = mul2(c2, o[p]);   // reuse sK
        __syncwarp();

        const int jn = lane & 15;
        float cs0 = 0.0f, cs1 = 0.0f;
        #pragma unroll
        for (int r = 0; r < 32; r += 2) {
            cs0 += sK[r * 18 + jn];
            cs1 += sK[(r + 1) * 18 + jn];
        }
        float z  = cs0 + cs1;
        float Rv = tanhf(z);                // accurate: feeds output directly
        float R2 = Rv * Rv;

        // row total across the 16 agent columns (lanes 0-15 / 16-31 mirrored)
        float tot = R2;
        tot += __shfl_xor_sync(0xffffffffu, tot, 8);
        tot += __shfl_xor_sync(0xffffffffu, tot, 4);
        tot += __shfl_xor_sync(0xffffffffu, tot, 2);
        tot += __shfl_xor_sync(0xffffffffu, tot, 1);

        const int ii = b & 15;
        if (lane < 16)
            out[(size_t)b * 16 + jn] = (jn == ii) ? tot : -R2;
        __syncwarp();
    }
}

extern "C" void kernel_launch(void* const* d_in, const int* in_sizes, int n_in,
                              void* d_out, int out_size)
{
    const float* x  = (const float*)d_in[0];
    const float* L  = (const float*)d_in[1];
    const float* Aq = (const float*)d_in[2];
    const float* Ak = (const float*)d_in[3];
    const float* Av = (const float*)d_in[4];
    const float* Ao = (const float*)d_in[5];
    float* out = (float*)d_out;

    int B = in_sizes[0] / (64 * 16);          // 65536
    int blocks = B / (WARPS * NB);            // 2048

    cudaFuncSetAttribute(att_mask_kernel,
                         cudaFuncAttributeMaxDynamicSharedMemorySize, SMEM_BYTES);
    att_mask_kernel<<<blocks, WARPS * 32, SMEM_BYTES>>>(x, L, Aq, Ak, Av, Ao, out);
}

// round 7
// speedup vs baseline: 1.0014x; 1.0014x over previous
#include <cuda_runtime.h>

// ---------------------------------------------------------------------------
// Att_mask: per batch item b (65536 of them):
//   Q = tanh(Aq @ x_b), K = tanh(Ak @ x_b), V = tanh(Av @ x_b)   ([32,16] each)
//   scores = Q K^T / sqrt(nn_b); attn = softmax(scores, axis=s)
//   o = attn @ V ; R = tanh(Ao @ o)  ([16])
//   out row (b = s*16+i): out[b,j] = (j==i) ? sum_j R2[j] : -R2[j],  R2 = R^2
//
// Strategy: one warp per batch item (lane = rank r), packed f32x2 FFMA
// (fma.rn.f32x2 -> FFMA2, 2x fp32 throughput), A matrices transposed in
// shared (conflict-free lane reads), x/K/V staged in per-warp shared.
// Online softmax (|score| <= 16 so exp never overflows; no max pass, no
// 32-register score array).
// ---------------------------------------------------------------------------

typedef unsigned long long u64;

__device__ __forceinline__ u64 ff2(u64 a, u64 b, u64 c) {
    u64 d; asm("fma.rn.f32x2 %0, %1, %2, %3;" : "=l"(d) : "l"(a), "l"(b), "l"(c)); return d;
}
__device__ __forceinline__ u64 mul2(u64 a, u64 b) {
    u64 d; asm("mul.rn.f32x2 %0, %1, %2;" : "=l"(d) : "l"(a), "l"(b)); return d;
}
__device__ __forceinline__ u64 dup2(float a) {
    u64 d; asm("mov.b64 %0, {%1, %1};" : "=l"(d) : "f"(a)); return d;
}
__device__ __forceinline__ float2 un2(u64 a) {
    float2 f; asm("mov.b64 {%0, %1}, %2;" : "=f"(f.x), "=f"(f.y) : "l"(a)); return f;
}
__device__ __forceinline__ u64 pk2(float x, float y) {
    u64 d; asm("mov.b64 %0, {%1, %2};" : "=l"(d) : "f"(x), "f"(y)); return d;
}
__device__ __forceinline__ float tanh_approx(float x) {
    float y; asm("tanh.approx.f32 %0, %1;" : "=f"(y) : "f"(x)); return y;
}

static constexpr int WARPS = 8;     // warps per block
static constexpr int NB    = 4;     // batch items per warp
// shared layout (floats):
//   sAq[64*32] sAk[64*32] sAv[64*32] sAo[32]   = 6176
//   per warp: x[64*16]=1024, K[32*18]=576, V[32*18]=576  -> 2176
static constexpr int A_FLOATS  = 3 * 2048 + 32;       // 6176
static constexpr int PW_FLOATS = 1024 + 576 + 576;    // 2176
static constexpr int SMEM_BYTES = (A_FLOATS + WARPS * PW_FLOATS) * 4;  // 94336

__global__ void __launch_bounds__(WARPS * 32, 2)
att_mask_kernel(const float* __restrict__ x, const float* __restrict__ L,
                const float* __restrict__ Aq, const float* __restrict__ Ak,
                const float* __restrict__ Av, const float* __restrict__ Ao,
                float* __restrict__ out)
{
    extern __shared__ float smem[];
    float* sAq = smem;            // [64][32], sAq[d*32+r] = Aq[r*64+d]
    float* sAk = smem + 2048;
    float* sAv = smem + 4096;
    float* sAo = smem + 6144;     // [32]

    const int tid = threadIdx.x;

    // Load A transposed: conflict-free broadcast-free lane-indexed reads later.
    for (int i = tid; i < 2048; i += WARPS * 32) {
        int d = i >> 5, r = i & 31;
        sAq[i] = Aq[r * 64 + d];
        sAk[i] = Ak[r * 64 + d];
        sAv[i] = Av[r * 64 + d];
    }
    if (tid < 32) sAo[tid] = Ao[tid];
    __syncthreads();

    const int w    = tid >> 5;
    const int lane = tid & 31;

    float* sx = smem + A_FLOATS + w * PW_FLOATS;   // [64][16]
    float* sK = sx + 1024;                         // [32] rows, stride 18
    float* sV = sK + 576;                          // [32] rows, stride 18

    const float aor = sAo[lane];

    for (int jj = 0; jj < NB; jj++) {
        const int b = (blockIdx.x * WARPS + w) * NB + jj;

        // --- stage x_b (64x16 fp32 = 4KB, contiguous) into shared ---
        {
            const float4* xg = (const float4*)(x + (size_t)b * 1024);
            float4* xs = (float4*)sx;
            #pragma unroll
            for (int i = 0; i < 8; i++)
                xs[i * 32 + lane] = xg[i * 32 + lane];
        }

        // --- num_neighbors from L[b,0,:] (values are exactly 0.0/1.0) ---
        float Lv = 0.0f;
        if (lane < 16) Lv = L[(size_t)b * 256 + lane];
        unsigned msk = __ballot_sync(0xffffffffu, Lv >= 1.0f);
        float nn = (float)(__popc(msk) + 1);
        float rs = rsqrtf(nn);
        __syncwarp();

        // --- projections: lane r accumulates Q/K/V row r over d, packed x2 ---
        u64 q[8], k[8], v[8];
        #pragma unroll
        for (int p = 0; p < 8; p++) { q[p] = 0ull; k[p] = 0ull; v[p] = 0ull; }

        #pragma unroll 4
        for (int d = 0; d < 64; d++) {
            const ulonglong2* xr = (const ulonglong2*)(sx + d * 16);
            ulonglong2 xa = xr[0], xb = xr[1], xc = xr[2], xd = xr[3];
            u64 aq = dup2(sAq[d * 32 + lane]);
            u64 ak = dup2(sAk[d * 32 + lane]);
            u64 av = dup2(sAv[d * 32 + lane]);
            q[0] = ff2(aq, xa.x, q[0]); q[1] = ff2(aq, xa.y, q[1]);
            q[2] = ff2(aq, xb.x, q[2]); q[3] = ff2(aq, xb.y, q[3]);
            q[4] = ff2(aq, xc.x, q[4]); q[5] = ff2(aq, xc.y, q[5]);
            q[6] = ff2(aq, xd.x, q[6]); q[7] = ff2(aq, xd.y, q[7]);
            k[0] = ff2(ak, xa.x, k[0]); k[1] = ff2(ak, xa.y, k[1]);
            k[2] = ff2(ak, xb.x, k[2]); k[3] = ff2(ak, xb.y, k[3]);
            k[4] = ff2(ak, xc.x, k[4]); k[5] = ff2(ak, xc.y, k[5]);
            k[6] = ff2(ak, xd.x, k[6]); k[7] = ff2(ak, xd.y, k[7]);
            v[0] = ff2(av, xa.x, v[0]); v[1] = ff2(av, xa.y, v[1]);
            v[2] = ff2(av, xb.x, v[2]); v[3] = ff2(av, xb.y, v[3]);
            v[4] = ff2(av, xc.x, v[4]); v[5] = ff2(av, xc.y, v[5]);
            v[6] = ff2(av, xd.x, v[6]); v[7] = ff2(av, xd.y, v[7]);
        }

        // --- tanh; fold 1/sqrt(nn) into Q; publish K,V rows to shared ---
        {
            u64 rs2 = dup2(rs);
            #pragma unroll
            for (int p = 0; p < 8; p++) {
                float2 fq = un2(q[p]);
                q[p] = mul2(pk2(tanh_approx(fq.x), tanh_approx(fq.y)), rs2);
                float2 fk = un2(k[p]);
                *(u64*)(sK + lane * 18 + 2 * p) = pk2(tanh_approx(fk.x), tanh_approx(fk.y));
                float2 fv = un2(v[p]);
                *(u64*)(sV + lane * 18 + 2 * p) = pk2(tanh_approx(fv.x), tanh_approx(fv.y));
            }
        }
        __syncwarp();

        // --- fused scores + softmax-numerator + o accumulation ---
        // |score| <= n / sqrt(nn) <= 16 -> exp() safe without max subtraction.
        u64 o[8];
        #pragma unroll
        for (int p = 0; p < 8; p++) o[p] = 0ull;
        float esum = 0.0f;

        #pragma unroll 4
        for (int s = 0; s < 32; s++) {
            const u64* kr = (const u64*)(sK + s * 18);
            u64 acc = mul2(q[0], kr[0]);
            #pragma unroll
            for (int p = 1; p < 8; p++) acc = ff2(q[p], kr[p], acc);
            float2 a2 = un2(acc);
            float e = __expf(a2.x + a2.y);
            esum += e;
            u64 e2 = dup2(e);
            const u64* vr = (const u64*)(sV + s * 18);
            #pragma unroll
            for (int p = 0; p < 8; p++) o[p] = ff2(e2, vr[p], o[p]);
        }

        // --- contribution c[r][n] = (Ao[r]/esum) * o[r][n], reduce over r ---
        float coef = aor / esum;
        u64 c2 = dup2(coef);
        __syncwarp();                       // done reading sK rows
        #pragma unroll
        for (int p = 0; p < 8; p++)
            *(u64*)(sK + lane * 18 + 2 * p) = mul2(c2, o[p]);   // reuse sK
        __syncwarp();

        const int jn = lane & 15;
        float cs0 = 0.0f, cs1 = 0.0f;
        #pragma unroll
        for (int r = 0; r < 32; r += 2) {
            cs0 += sK[r * 18 + jn];
            cs1 += sK[(r + 1) * 18 + jn];
        }
        float z  = cs0 + cs1;
        float Rv = tanhf(z);                // accurate: feeds output directly
        float R2 = Rv * Rv;

        // row total across the 16 agent columns (lanes 0-15 / 16-31 mirrored)
        float tot = R2;
        tot += __shfl_xor_sync(0xffffffffu, tot, 8);
        tot += __shfl_xor_sync(0xffffffffu, tot, 4);
        tot += __shfl_xor_sync(0xffffffffu, tot, 2);
        tot += __shfl_xor_sync(0xffffffffu, tot, 1);

        const int ii = b & 15;
        if (lane < 16)
            out[(size_t)b * 16 + jn] = (jn == ii) ? tot : -R2;
        __syncwarp();
    }
}

extern "C" void kernel_launch(void* const* d_in, const int* in_sizes, int n_in,
                              void* d_out, int out_size)
{
    const float* x  = (const float*)d_in[0];
    const float* L  = (const float*)d_in[1];
    const float* Aq = (const float*)d_in[2];
    const float* Ak = (const float*)d_in[3];
    const float* Av = (const float*)d_in[4];
    const float* Ao = (const float*)d_in[5];
    float* out = (float*)d_out;

    int B = in_sizes[0] / (64 * 16);          // 65536
    int blocks = B / (WARPS * NB);            // 2048

    cudaFuncSetAttribute(att_mask_kernel,
                         cudaFuncAttributeMaxDynamicSharedMemorySize, SMEM_BYTES);
    att_mask_kernel<<<blocks, WARPS * 32, SMEM_BYTES>>>(x, L, Aq, Ak, Av, Ao, out);
}

// round 8
// speedup vs baseline: 1.0016x; 1.0002x over previous
#include <cuda_runtime.h>

// ---------------------------------------------------------------------------
// Att_mask: per batch item b (65536 of them):
//   Q = tanh(Aq @ x_b), K = tanh(Ak @ x_b), V = tanh(Av @ x_b)   ([32,16] each)
//   scores = Q K^T / sqrt(nn_b); attn = softmax(scores, axis=s)
//   o = attn @ V ; R = tanh(Ao @ o)  ([16])
//   out row (b = s*16+i): out[b,j] = (j==i) ? sum_j R2[j] : -R2[j],  R2 = R^2
//
// Strategy: one warp per batch item (lane = rank r), packed f32x2 FFMA
// (fma.rn.f32x2 -> FFMA2, 2x fp32 throughput), A matrices transposed in
// shared (conflict-free lane reads), x/K/V staged in per-warp shared.
// Online softmax (|score| <= 16 so exp never overflows; no max pass, no
// 32-register score array).
// ---------------------------------------------------------------------------

typedef unsigned long long u64;

__device__ __forceinline__ u64 ff2(u64 a, u64 b, u64 c) {
    u64 d; asm("fma.rn.f32x2 %0, %1, %2, %3;" : "=l"(d) : "l"(a), "l"(b), "l"(c)); return d;
}
__device__ __forceinline__ u64 mul2(u64 a, u64 b) {
    u64 d; asm("mul.rn.f32x2 %0, %1, %2;" : "=l"(d) : "l"(a), "l"(b)); return d;
}
__device__ __forceinline__ u64 dup2(float a) {
    u64 d; asm("mov.b64 %0, {%1, %1};" : "=l"(d) : "f"(a)); return d;
}
__device__ __forceinline__ float2 un2(u64 a) {
    float2 f; asm("mov.b64 {%0, %1}, %2;" : "=f"(f.x), "=f"(f.y) : "l"(a)); return f;
}
__device__ __forceinline__ u64 pk2(float x, float y) {
    u64 d; asm("mov.b64 %0, {%1, %2};" : "=l"(d) : "f"(x), "f"(y)); return d;
}
__device__ __forceinline__ float tanh_approx(float x) {
    float y; asm("tanh.approx.f32 %0, %1;" : "=f"(y) : "f"(x)); return y;
}

static constexpr int WARPS = 8;     // warps per block
static constexpr int NB    = 4;     // batch items per warp
// shared layout (floats):
//   sAq[64*32] sAk[64*32] sAv[64*32] sAo[32]   = 6176
//   per warp: x[64*16]=1024, K[32*18]=576, V[32*18]=576  -> 2176
static constexpr int A_FLOATS  = 3 * 2048 + 32;       // 6176
static constexpr int PW_FLOATS = 1024 + 576 + 576;    // 2176
static constexpr int SMEM_BYTES = (A_FLOATS + WARPS * PW_FLOATS) * 4;  // 94336

__global__ void __launch_bounds__(WARPS * 32, 2)
att_mask_kernel(const float* __restrict__ x, const float* __restrict__ L,
                const float* __restrict__ Aq, const float* __restrict__ Ak,
                const float* __restrict__ Av, const float* __restrict__ Ao,
                float* __restrict__ out)
{
    extern __shared__ float smem[];
    float* sAq = smem;            // [64][32], sAq[d*32+r] = Aq[r*64+d]
    float* sAk = smem + 2048;
    float* sAv = smem + 4096;
    float* sAo = smem + 6144;     // [32]

    const int tid = threadIdx.x;

    // Load A transposed: conflict-free broadcast-free lane-indexed reads later.
    for (int i = tid; i < 2048; i += WARPS * 32) {
        int d = i >> 5, r = i & 31;
        sAq[i] = Aq[r * 64 + d];
        sAk[i] = Ak[r * 64 + d];
        sAv[i] = Av[r * 64 + d];
    }
    if (tid < 32) sAo[tid] = Ao[tid];
    __syncthreads();

    const int w    = tid >> 5;
    const int lane = tid & 31;

    float* sx = smem + A_FLOATS + w * PW_FLOATS;   // [64][16]
    float* sK = sx + 1024;                         // [32] rows, stride 18
    float* sV = sK + 576;                          // [32] rows, stride 18

    const float aor = sAo[lane];

    for (int jj = 0; jj < NB; jj++) {
        const int b = (blockIdx.x * WARPS + w) * NB + jj;

        // --- stage x_b (64x16 fp32 = 4KB, contiguous) into shared ---
        {
            const float4* xg = (const float4*)(x + (size_t)b * 1024);
            float4* xs = (float4*)sx;
            #pragma unroll
            for (int i = 0; i < 8; i++)
                xs[i * 32 + lane] = xg[i * 32 + lane];
        }

        // --- num_neighbors from L[b,0,:] (values are exactly 0.0/1.0) ---
        float Lv = 0.0f;
        if (lane < 16) Lv = L[(size_t)b * 256 + lane];
        unsigned msk = __ballot_sync(0xffffffffu, Lv >= 1.0f);
        float nn = (float)(__popc(msk) + 1);
        float rs = rsqrtf(nn);
        __syncwarp();

        // --- projections: lane r accumulates Q/K/V row r over d, packed x2 ---
        u64 q[8], k[8], v[8];
        #pragma unroll
        for (int p = 0; p < 8; p++) { q[p] = 0ull; k[p] = 0ull; v[p] = 0ull; }

        #pragma unroll 4
        for (int d = 0; d < 64; d++) {
            const ulonglong2* xr = (const ulonglong2*)(sx + d * 16);
            ulonglong2 xa = xr[0], xb = xr[1], xc = xr[2], xd = xr[3];
            u64 aq = dup2(sAq[d * 32 + lane]);
            u64 ak = dup2(sAk[d * 32 + lane]);
            u64 av = dup2(sAv[d * 32 + lane]);
            q[0] = ff2(aq, xa.x, q[0]); q[1] = ff2(aq, xa.y, q[1]);
            q[2] = ff2(aq, xb.x, q[2]); q[3] = ff2(aq, xb.y, q[3]);
            q[4] = ff2(aq, xc.x, q[4]); q[5] = ff2(aq, xc.y, q[5]);
            q[6] = ff2(aq, xd.x, q[6]); q[7] = ff2(aq, xd.y, q[7]);
            k[0] = ff2(ak, xa.x, k[0]); k[1] = ff2(ak, xa.y, k[1]);
            k[2] = ff2(ak, xb.x, k[2]); k[3] = ff2(ak, xb.y, k[3]);
            k[4] = ff2(ak, xc.x, k[4]); k[5] = ff2(ak, xc.y, k[5]);
            k[6] = ff2(ak, xd.x, k[6]); k[7] = ff2(ak, xd.y, k[7]);
            v[0] = ff2(av, xa.x, v[0]); v[1] = ff2(av, xa.y, v[1]);
            v[2] = ff2(av, xb.x, v[2]); v[3] = ff2(av, xb.y, v[3]);
            v[4] = ff2(av, xc.x, v[4]); v[5] = ff2(av, xc.y, v[5]);
            v[6] = ff2(av, xd.x, v[6]); v[7] = ff2(av, xd.y, v[7]);
        }

        // --- tanh; fold 1/sqrt(nn) into Q; publish K,V rows to shared ---
        {
            u64 rs2 = dup2(rs);
            #pragma unroll
            for (int p = 0; p < 8; p++) {
                float2 fq = un2(q[p]);
                q[p] = mul2(pk2(tanh_approx(fq.x), tanh_approx(fq.y)), rs2);
                float2 fk = un2(k[p]);
                *(u64*)(sK + lane * 18 + 2 * p) = pk2(tanh_approx(fk.x), tanh_approx(fk.y));
                float2 fv = un2(v[p]);
                *(u64*)(sV + lane * 18 + 2 * p) = pk2(tanh_approx(fv.x), tanh_approx(fv.y));
            }
        }
        __syncwarp();

        // --- fused scores + softmax-numerator + o accumulation ---
        // |score| <= n / sqrt(nn) <= 16 -> exp() safe without max subtraction.
        u64 o[8];
        #pragma unroll
        for (int p = 0; p < 8; p++) o[p] = 0ull;
        float esum = 0.0f;

        #pragma unroll 4
        for (int s = 0; s < 32; s++) {
            const u64* kr = (const u64*)(sK + s * 18);
            u64 acc = mul2(q[0], kr[0]);
            #pragma unroll
            for (int p = 1; p < 8; p++) acc = ff2(q[p], kr[p], acc);
            float2 a2 = un2(acc);
            float e = __expf(a2.x + a2.y);
            esum += e;
            u64 e2 = dup2(e);
            const u64* vr = (const u64*)(sV + s * 18);
            #pragma unroll
            for (int p = 0; p < 8; p++) o[p] = ff2(e2, vr[p], o[p]);
        }

        // --- contribution c[r][n] = (Ao[r]/esum) * o[r][n], reduce over r ---
        float coef = aor / esum;
        u64 c2 = dup2(coef);
        __syncwarp();                       // done reading sK rows
        #pragma unroll
        for (int p = 0; p < 8; p++)
            *(u64*)(sK + lane * 18 + 2 * p) = mul2(c2, o[p]);   // reuse sK
        __syncwarp();

        const int jn = lane & 15;
        float cs0 = 0.0f, cs1 = 0.0f;
        #pragma unroll
        for (int r = 0; r < 32; r += 2) {
            cs0 += sK[r * 18 + jn];
            cs1 += sK[(r + 1) * 18 + jn];
        }
        float z  = cs0 + cs1;
        float Rv = tanhf(z);                // accurate: feeds output directly
        float R2 = Rv * Rv;

        // row total across the 16 agent columns (lanes 0-15 / 16-31 mirrored)
        float tot = R2;
        tot += __shfl_xor_sync(0xffffffffu, tot, 8);
        tot += __shfl_xor_sync(0xffffffffu, tot, 4);
        tot += __shfl_xor_sync(0xffffffffu, tot, 2);
        tot += __shfl_xor_sync(0xffffffffu, tot, 1);

        const int ii = b & 15;
        if (lane < 16)
            out[(size_t)b * 16 + jn] = (jn == ii) ? tot : -R2;
        __syncwarp();
    }
}

extern "C" void kernel_launch(void* const* d_in, const int* in_sizes, int n_in,
                              void* d_out, int out_size)
{
    const float* x  = (const float*)d_in[0];
    const float* L  = (const float*)d_in[1];
    const float* Aq = (const float*)d_in[2];
    const float* Ak = (const float*)d_in[3];
    const float* Av = (const float*)d_in[4];
    const float* Ao = (const float*)d_in[5];
    float* out = (float*)d_out;

    int B = in_sizes[0] / (64 * 16);          // 65536
    int blocks = B / (WARPS * NB);            // 2048

    cudaFuncSetAttribute(att_mask_kernel,
                         cudaFuncAttributeMaxDynamicSharedMemorySize, SMEM_BYTES);
    att_mask_kernel<<<blocks, WARPS * 32, SMEM_BYTES>>>(x, L, Aq, Ak, Av, Ao, out);
}

// round 9
// speedup vs baseline: 1.0019x; 1.0002x over previous
#include <cuda_runtime.h>

// ---------------------------------------------------------------------------
// Att_mask: per batch item b (65536 of them):
//   Q = tanh(Aq @ x_b), K = tanh(Ak @ x_b), V = tanh(Av @ x_b)   ([32,16] each)
//   scores = Q K^T / sqrt(nn_b); attn = softmax(scores, axis=s)
//   o = attn @ V ; R = tanh(Ao @ o)  ([16])
//   out row (b = s*16+i): out[b,j] = (j==i) ? sum_j R2[j] : -R2[j],  R2 = R^2
//
// Strategy: one warp per batch item (lane = rank r), packed f32x2 FFMA
// (fma.rn.f32x2 -> FFMA2, 2x fp32 throughput), A matrices transposed in
// shared (conflict-free lane reads), x/K/V staged in per-warp shared.
// Online softmax (|score| <= 16 so exp never overflows; no max pass, no
// 32-register score array).
// ---------------------------------------------------------------------------

typedef unsigned long long u64;

__device__ __forceinline__ u64 ff2(u64 a, u64 b, u64 c) {
    u64 d; asm("fma.rn.f32x2 %0, %1, %2, %3;" : "=l"(d) : "l"(a), "l"(b), "l"(c)); return d;
}
__device__ __forceinline__ u64 mul2(u64 a, u64 b) {
    u64 d; asm("mul.rn.f32x2 %0, %1, %2;" : "=l"(d) : "l"(a), "l"(b)); return d;
}
__device__ __forceinline__ u64 dup2(float a) {
    u64 d; asm("mov.b64 %0, {%1, %1};" : "=l"(d) : "f"(a)); return d;
}
__device__ __forceinline__ float2 un2(u64 a) {
    float2 f; asm("mov.b64 {%0, %1}, %2;" : "=f"(f.x), "=f"(f.y) : "l"(a)); return f;
}
__device__ __forceinline__ u64 pk2(float x, float y) {
    u64 d; asm("mov.b64 %0, {%1, %2};" : "=l"(d) : "f"(x), "f"(y)); return d;
}
__device__ __forceinline__ float tanh_approx(float x) {
    float y; asm("tanh.approx.f32 %0, %1;" : "=f"(y) : "f"(x)); return y;
}

static constexpr int WARPS = 8;     // warps per block
static constexpr int NB    = 4;     // batch items per warp
// shared layout (floats):
//   sAq[64*32] sAk[64*32] sAv[64*32] sAo[32]   = 6176
//   per warp: x[64*16]=1024, K[32*18]=576, V[32*18]=576  -> 2176
static constexpr int A_FLOATS  = 3 * 2048 + 32;       // 6176
static constexpr int PW_FLOATS = 1024 + 576 + 576;    // 2176
static constexpr int SMEM_BYTES = (A_FLOATS + WARPS * PW_FLOATS) * 4;  // 94336

__global__ void __launch_bounds__(WARPS * 32, 2)
att_mask_kernel(const float* __restrict__ x, const float* __restrict__ L,
                const float* __restrict__ Aq, const float* __restrict__ Ak,
                const float* __restrict__ Av, const float* __restrict__ Ao,
                float* __restrict__ out)
{
    extern __shared__ float smem[];
    float* sAq = smem;            // [64][32], sAq[d*32+r] = Aq[r*64+d]
    float* sAk = smem + 2048;
    float* sAv = smem + 4096;
    float* sAo = smem + 6144;     // [32]

    const int tid = threadIdx.x;

    // Load A transposed: conflict-free broadcast-free lane-indexed reads later.
    for (int i = tid; i < 2048; i += WARPS * 32) {
        int d = i >> 5, r = i & 31;
        sAq[i] = Aq[r * 64 + d];
        sAk[i] = Ak[r * 64 + d];
        sAv[i] = Av[r * 64 + d];
    }
    if (tid < 32) sAo[tid] = Ao[tid];
    __syncthreads();

    const int w    = tid >> 5;
    const int lane = tid & 31;

    float* sx = smem + A_FLOATS + w * PW_FLOATS;   // [64][16]
    float* sK = sx + 1024;                         // [32] rows, stride 18
    float* sV = sK + 576;                          // [32] rows, stride 18

    const float aor = sAo[lane];

    for (int jj = 0; jj < NB; jj++) {
        const int b = (blockIdx.x * WARPS + w) * NB + jj;

        // --- stage x_b (64x16 fp32 = 4KB, contiguous) into shared ---
        {
            const float4* xg = (const float4*)(x + (size_t)b * 1024);
            float4* xs = (float4*)sx;
            #pragma unroll
            for (int i = 0; i < 8; i++)
                xs[i * 32 + lane] = xg[i * 32 + lane];
        }

        // --- num_neighbors from L[b,0,:] (values are exactly 0.0/1.0) ---
        float Lv = 0.0f;
        if (lane < 16) Lv = L[(size_t)b * 256 + lane];
        unsigned msk = __ballot_sync(0xffffffffu, Lv >= 1.0f);
        float nn = (float)(__popc(msk) + 1);
        float rs = rsqrtf(nn);
        __syncwarp();

        // --- projections: lane r accumulates Q/K/V row r over d, packed x2 ---
        u64 q[8], k[8], v[8];
        #pragma unroll
        for (int p = 0; p < 8; p++) { q[p] = 0ull; k[p] = 0ull; v[p] = 0ull; }

        #pragma unroll 4
        for (int d = 0; d < 64; d++) {
            const ulonglong2* xr = (const ulonglong2*)(sx + d * 16);
            ulonglong2 xa = xr[0], xb = xr[1], xc = xr[2], xd = xr[3];
            u64 aq = dup2(sAq[d * 32 + lane]);
            u64 ak = dup2(sAk[d * 32 + lane]);
            u64 av = dup2(sAv[d * 32 + lane]);
            q[0] = ff2(aq, xa.x, q[0]); q[1] = ff2(aq, xa.y, q[1]);
            q[2] = ff2(aq, xb.x, q[2]); q[3] = ff2(aq, xb.y, q[3]);
            q[4] = ff2(aq, xc.x, q[4]); q[5] = ff2(aq, xc.y, q[5]);
            q[6] = ff2(aq, xd.x, q[6]); q[7] = ff2(aq, xd.y, q[7]);
            k[0] = ff2(ak, xa.x, k[0]); k[1] = ff2(ak, xa.y, k[1]);
            k[2] = ff2(ak, xb.x, k[2]); k[3] = ff2(ak, xb.y, k[3]);
            k[4] = ff2(ak, xc.x, k[4]); k[5] = ff2(ak, xc.y, k[5]);
            k[6] = ff2(ak, xd.x, k[6]); k[7] = ff2(ak, xd.y, k[7]);
            v[0] = ff2(av, xa.x, v[0]); v[1] = ff2(av, xa.y, v[1]);
            v[2] = ff2(av, xb.x, v[2]); v[3] = ff2(av, xb.y, v[3]);
            v[4] = ff2(av, xc.x, v[4]); v[5] = ff2(av, xc.y, v[5]);
            v[6] = ff2(av, xd.x, v[6]); v[7] = ff2(av, xd.y, v[7]);
        }

        // --- tanh; fold 1/sqrt(nn) into Q; publish K,V rows to shared ---
        {
            u64 rs2 = dup2(rs);
            #pragma unroll
            for (int p = 0; p < 8; p++) {
                float2 fq = un2(q[p]);
                q[p] = mul2(pk2(tanh_approx(fq.x), tanh_approx(fq.y)), rs2);
                float2 fk = un2(k[p]);
                *(u64*)(sK + lane * 18 + 2 * p) = pk2(tanh_approx(fk.x), tanh_approx(fk.y));
                float2 fv = un2(v[p]);
                *(u64*)(sV + lane * 18 + 2 * p) = pk2(tanh_approx(fv.x), tanh_approx(fv.y));
            }
        }
        __syncwarp();

        // --- fused scores + softmax-numerator + o accumulation ---
        // |score| <= n / sqrt(nn) <= 16 -> exp() safe without max subtraction.
        u64 o[8];
        #pragma unroll
        for (int p = 0; p < 8; p++) o[p] = 0ull;
        float esum = 0.0f;

        #pragma unroll 4
        for (int s = 0; s < 32; s++) {
            const u64* kr = (const u64*)(sK + s * 18);
            u64 acc = mul2(q[0], kr[0]);
            #pragma unroll
            for (int p = 1; p < 8; p++) acc = ff2(q[p], kr[p], acc);
            float2 a2 = un2(acc);
            float e = __expf(a2.x + a2.y);
            esum += e;
            u64 e2 = dup2(e);
            const u64* vr = (const u64*)(sV + s * 18);
            #pragma unroll
            for (int p = 0; p < 8; p++) o[p] = ff2(e2, vr[p], o[p]);
        }

        // --- contribution c[r][n] = (Ao[r]/esum) * o[r][n], reduce over r ---
        float coef = aor / esum;
        u64 c2 = dup2(coef);
        __syncwarp();                       // done reading sK rows
        #pragma unroll
        for (int p = 0; p < 8; p++)
            *(u64*)(sK + lane * 18 + 2 * p) = mul2(c2, o[p]);   // reuse sK
        __syncwarp();

        const int jn = lane & 15;
        float cs0 = 0.0f, cs1 = 0.0f;
        #pragma unroll
        for (int r = 0; r < 32; r += 2) {
            cs0 += sK[r * 18 + jn];
            cs1 += sK[(r + 1) * 18 + jn];
        }
        float z  = cs0 + cs1;
        float Rv = tanhf(z);                // accurate: feeds output directly
        float R2 = Rv * Rv;

        // row total across the 16 agent columns (lanes 0-15 / 16-31 mirrored)
        float tot = R2;
        tot += __shfl_xor_sync(0xffffffffu, tot, 8);
        tot += __shfl_xor_sync(0xffffffffu, tot, 4);
        tot += __shfl_xor_sync(0xffffffffu, tot, 2);
        tot += __shfl_xor_sync(0xffffffffu, tot, 1);

        const int ii = b & 15;
        if (lane < 16)
            out[(size_t)b * 16 + jn] = (jn == ii) ? tot : -R2;
        __syncwarp();
    }
}

extern "C" void kernel_launch(void* const* d_in, const int* in_sizes, int n_in,
                              void* d_out, int out_size)
{
    const float* x  = (const float*)d_in[0];
    const float* L  = (const float*)d_in[1];
    const float* Aq = (const float*)d_in[2];
    const float* Ak = (const float*)d_in[3];
    const float* Av = (const float*)d_in[4];
    const float* Ao = (const float*)d_in[5];
    float* out = (float*)d_out;

    int B = in_sizes[0] / (64 * 16);          // 65536
    int blocks = B / (WARPS * NB);            // 2048

    cudaFuncSetAttribute(att_mask_kernel,
                         cudaFuncAttributeMaxDynamicSharedMemorySize, SMEM_BYTES);
    att_mask_kernel<<<blocks, WARPS * 32, SMEM_BYTES>>>(x, L, Aq, Ak, Av, Ao, out);
}

// round 10
// speedup vs baseline: 1.0068x; 1.0049x over previous
#include <cuda_runtime.h>

// ---------------------------------------------------------------------------
// Att_mask, one warp per batch item (lane = rank r), packed f32x2 FFMA.
// R9 -> R10 changes (LSU-pipe was binding at 83%):
//  - A matrices packed as float4 (aq,ak,av,0):  1 LDS.128/d instead of 3 LDS.32
//  - K/V rows stride 20 floats (16B aligned) -> 4 LDS.128 per row in scores
//    loop (was 8 LDS.64); writes chunk-rotated by (row>>3)&3 for conflict-free
//    STS.128, un-rotated at read with compile-time indices.
//  - sK/sV alias the x staging buffer (x dead after projection): smem 94->74KB
//  - vectorized publish / halved reduction loads
// ---------------------------------------------------------------------------

typedef unsigned long long u64;

__device__ __forceinline__ u64 ff2(u64 a, u64 b, u64 c) {
    u64 d; asm("fma.rn.f32x2 %0, %1, %2, %3;" : "=l"(d) : "l"(a), "l"(b), "l"(c)); return d;
}
__device__ __forceinline__ u64 mul2(u64 a, u64 b) {
    u64 d; asm("mul.rn.f32x2 %0, %1, %2;" : "=l"(d) : "l"(a), "l"(b)); return d;
}
__device__ __forceinline__ u64 dup2(float a) {
    u64 d; asm("mov.b64 %0, {%1, %1};" : "=l"(d) : "f"(a)); return d;
}
__device__ __forceinline__ float2 un2(u64 a) {
    float2 f; asm("mov.b64 {%0, %1}, %2;" : "=f"(f.x), "=f"(f.y) : "l"(a)); return f;
}
__device__ __forceinline__ u64 pk2(float x, float y) {
    u64 d; asm("mov.b64 %0, {%1, %2};" : "=l"(d) : "f"(x), "f"(y)); return d;
}
__device__ __forceinline__ float tanh_approx(float x) {
    float y; asm("tanh.approx.f32 %0, %1;" : "=f"(y) : "f"(x)); return y;
}

static constexpr int WARPS = 8;     // warps per block
static constexpr int NB    = 4;     // batch items per warp
// shared layout (floats):
//   sA4: float4[64][32]  (aq,ak,av,0)               = 8192 floats
//   sAo: [32]                                       =   32
//   per warp: 1280-float region, used as
//       x[64][16] (1024) during projection, then aliased by
//       K rows [32] stride 20 (640) + V rows [32] stride 20 (640)
static constexpr int A4_FLOATS = 64 * 32 * 4;                     // 8192
static constexpr int A_TOT     = A4_FLOATS + 32;                  // 8224
static constexpr int PW_FLOATS = 1280;
static constexpr int SMEM_BYTES = (A_TOT + WARPS * PW_FLOATS) * 4; // 73856

__global__ void __launch_bounds__(WARPS * 32, 2)
att_mask_kernel(const float* __restrict__ x, const float* __restrict__ L,
                const float* __restrict__ Aq, const float* __restrict__ Ak,
                const float* __restrict__ Av, const float* __restrict__ Ao,
                float* __restrict__ out)
{
    extern __shared__ float smem[];
    float4* sA4 = (float4*)smem;          // [64][32]
    float*  sAo = smem + A4_FLOATS;       // [32]

    const int tid = threadIdx.x;

    // A packed+transposed: sA4[d*32+r] = (Aq[r][d], Ak[r][d], Av[r][d], 0)
    for (int i = tid; i < 2048; i += WARPS * 32) {
        int d = i >> 5, r = i & 31;
        sA4[i] = make_float4(Aq[r * 64 + d], Ak[r * 64 + d], Av[r * 64 + d], 0.f);
    }
    if (tid < 32) sAo[tid] = Ao[tid];
    __syncthreads();

    const int w    = tid >> 5;
    const int lane = tid & 31;

    float* sx = smem + A_TOT + w * PW_FLOATS;   // [64][16] during projection
    float* sK = sx;                             // aliased: 32 rows, stride 20
    float* sV = sx + 640;

    const float aor  = sAo[lane];
    const int   rotw = (lane >> 3) & 3;         // write-rotation for this row

    for (int jj = 0; jj < NB; jj++) {
        const int b = (blockIdx.x * WARPS + w) * NB + jj;

        // --- stage x_b (64x16 fp32 = 4KB contiguous) into shared ---
        {
            const float4* xg = (const float4*)(x + (size_t)b * 1024);
            float4* xs = (float4*)sx;
            #pragma unroll
            for (int i = 0; i < 8; i++)
                xs[i * 32 + lane] = xg[i * 32 + lane];
        }

        // --- num_neighbors from L[b,0,:] (values are exactly 0.0/1.0) ---
        float Lv = (lane < 16) ? L[(size_t)b * 256 + lane] : 0.0f;
        unsigned msk = __ballot_sync(0xffffffffu, Lv >= 1.0f);
        float rs = rsqrtf((float)(__popc(msk) + 1));
        __syncwarp();

        // --- projections: lane r accumulates Q/K/V row r over d, packed x2 ---
        u64 q[8], k[8], v[8];
        #pragma unroll
        for (int p = 0; p < 8; p++) { q[p] = 0ull; k[p] = 0ull; v[p] = 0ull; }

        #pragma unroll 4
        for (int d = 0; d < 64; d++) {
            const ulonglong2* xr = (const ulonglong2*)(sx + d * 16);
            ulonglong2 xa = xr[0], xb = xr[1], xc = xr[2], xd = xr[3];
            float4 a4 = sA4[d * 32 + lane];           // 1 LDS.128, conflict-free
            u64 aq = dup2(a4.x);
            u64 ak = dup2(a4.y);
            u64 av = dup2(a4.z);
            q[0] = ff2(aq, xa.x, q[0]); q[1] = ff2(aq, xa.y, q[1]);
            q[2] = ff2(aq, xb.x, q[2]); q[3] = ff2(aq, xb.y, q[3]);
            q[4] = ff2(aq, xc.x, q[4]); q[5] = ff2(aq, xc.y, q[5]);
            q[6] = ff2(aq, xd.x, q[6]); q[7] = ff2(aq, xd.y, q[7]);
            k[0] = ff2(ak, xa.x, k[0]); k[1] = ff2(ak, xa.y, k[1]);
            k[2] = ff2(ak, xb.x, k[2]); k[3] = ff2(ak, xb.y, k[3]);
            k[4] = ff2(ak, xc.x, k[4]); k[5] = ff2(ak, xc.y, k[5]);
            k[6] = ff2(ak, xd.x, k[6]); k[7] = ff2(ak, xd.y, k[7]);
            v[0] = ff2(av, xa.x, v[0]); v[1] = ff2(av, xa.y, v[1]);
            v[2] = ff2(av, xb.x, v[2]); v[3] = ff2(av, xb.y, v[3]);
            v[4] = ff2(av, xc.x, v[4]); v[5] = ff2(av, xc.y, v[5]);
            v[6] = ff2(av, xd.x, v[6]); v[7] = ff2(av, xd.y, v[7]);
        }
        __syncwarp();   // all lanes done reading sx; safe to overwrite with K/V

        // --- tanh; fold 1/sqrt(nn) into Q; publish K,V rows (chunk-rotated) ---
        {
            u64 rs2 = dup2(rs);
            #pragma unroll
            for (int p = 0; p < 8; p++) {
                float2 fq = un2(q[p]);
                q[p] = mul2(pk2(tanh_approx(fq.x), tanh_approx(fq.y)), rs2);
                float2 fk = un2(k[p]);
                k[p] = pk2(tanh_approx(fk.x), tanh_approx(fk.y));
                float2 fv = un2(v[p]);
                v[p] = pk2(tanh_approx(fv.x), tanh_approx(fv.y));
            }
            ulonglong2* kw = (ulonglong2*)(sK + lane * 20);
            ulonglong2* vw = (ulonglong2*)(sV + lane * 20);
            #pragma unroll
            for (int c = 0; c < 4; c++) {
                int pc = (c + rotw) & 3;   // rotated position: conflict-free STS.128
                kw[pc] = make_ulonglong2(k[2 * c], k[2 * c + 1]);
                vw[pc] = make_ulonglong2(v[2 * c], v[2 * c + 1]);
            }
        }
        __syncwarp();

        // --- fused scores + softmax-numerator + o accumulation ---
        // |score| <= 16 -> exp safe without max subtraction.
        u64 o[8];
        #pragma unroll
        for (int p = 0; p < 8; p++) o[p] = 0ull;
        float esum = 0.0f;

        #pragma unroll
        for (int s8 = 0; s8 < 4; s8++) {          // rows s8*8 .. s8*8+7 share rotation s8
            #pragma unroll
            for (int t = 0; t < 8; t++) {
                const int s = s8 * 8 + t;
                const ulonglong2* kr = (const ulonglong2*)(sK + s * 20);
                u64 acc = 0ull;
                #pragma unroll
                for (int p = 0; p < 4; p++) {
                    const int c = (p + 4 - s8) & 3;   // logical chunk at position p
                    ulonglong2 kk = kr[p];
                    acc = ff2(q[2 * c],     kk.x, acc);
                    acc = ff2(q[2 * c + 1], kk.y, acc);
                }
                float2 a2 = un2(acc);
                float e = __expf(a2.x + a2.y);
                esum += e;
                u64 e2 = dup2(e);
                const ulonglong2* vr = (const ulonglong2*)(sV + s * 20);
                #pragma unroll
                for (int p = 0; p < 4; p++) {
                    const int c = (p + 4 - s8) & 3;
                    ulonglong2 vv = vr[p];
                    o[2 * c]     = ff2(e2, vv.x, o[2 * c]);
                    o[2 * c + 1] = ff2(e2, vv.y, o[2 * c + 1]);
                }
            }
        }

        // --- contribution c[r][n] = (Ao[r]/esum) * o[r][n]; reduce over r ---
        float coef = __fdividef(aor, esum);
        u64 c2 = dup2(coef);
        __syncwarp();                       // everyone done reading sK rows
        {
            ulonglong2* cw = (ulonglong2*)(sK + lane * 20);  // plain layout
            #pragma unroll
            for (int c = 0; c < 4; c++)
                cw[c] = make_ulonglong2(mul2(c2, o[2 * c]), mul2(c2, o[2 * c + 1]));
        }
        __syncwarp();

        const int jn    = lane & 15;
        const int rbase = (lane >> 4) << 4;     // low lanes sum r=0..15, high r=16..31
        float cs0 = 0.0f, cs1 = 0.0f;
        #pragma unroll
        for (int r = 0; r < 16; r += 2) {
            cs0 += sK[(rbase + r) * 20 + jn];
            cs1 += sK[(rbase + r + 1) * 20 + jn];
        }
        float cs = cs0 + cs1;
        float z  = cs + __shfl_xor_sync(0xffffffffu, cs, 16);
        float Rv = tanhf(z);                // accurate: feeds output directly
        float R2 = Rv * Rv;

        float tot = R2;
        tot += __shfl_xor_sync(0xffffffffu, tot, 8);
        tot += __shfl_xor_sync(0xffffffffu, tot, 4);
        tot += __shfl_xor_sync(0xffffffffu, tot, 2);
        tot += __shfl_xor_sync(0xffffffffu, tot, 1);

        if (lane < 16)
            out[(size_t)b * 16 + jn] = (jn == (b & 15)) ? tot : -R2;
        __syncwarp();
    }
}

extern "C" void kernel_launch(void* const* d_in, const int* in_sizes, int n_in,
                              void* d_out, int out_size)
{
    const float* x  = (const float*)d_in[0];
    const float* L  = (const float*)d_in[1];
    const float* Aq = (const float*)d_in[2];
    const float* Ak = (const float*)d_in[3];
    const float* Av = (const float*)d_in[4];
    const float* Ao = (const float*)d_in[5];
    float* out = (float*)d_out;

    int B = in_sizes[0] / (64 * 16);          // 65536
    int blocks = B / (WARPS * NB);            // 2048

    cudaFuncSetAttribute(att_mask_kernel,
                         cudaFuncAttributeMaxDynamicSharedMemorySize, SMEM_BYTES);
    att_mask_kernel<<<blocks, WARPS * 32, SMEM_BYTES>>>(x, L, Aq, Ak, Av, Ao, out);
}